// round 15
// baseline (speedup 1.0000x reference)
#include <cuda_runtime.h>
#include <cuda_bf16.h>
#include <math_constants.h>
#include <cstdint>

namespace {

constexpr int TOKENS   = 16384;
constexpr int NEXP     = 64;
constexpr int KDIM     = 2048;
constexpr int K_TOP    = 6;
constexpr int TILE_M   = 64;         // tokens per CTA
constexpr int CHUNK    = 32;         // k per chunk
constexpr int NCHUNK   = KDIM / CHUNK;  // 64
constexpr int NTHREADS = 256;        // 8 warps: 2(M) x 2(N) x 2(Ksplit)
constexpr float FP32_MIN_NORMAL = 1.17549435e-38f;  // 2^-126

// bf16 tile rows padded to 80B (40 halves) -> ldmatrix conflict-free
constexpr int ROWB    = 80;
constexpr int A_TERM  = TILE_M * ROWB;        // 5120 B
constexpr int A_BUFSZ = 3 * A_TERM;           // 15360 B
constexpr int B_TERM  = NEXP * ROWB;          // 5120 B
constexpr int B_BUFSZ = 3 * B_TERM;           // 15360 B
constexpr int OFF_A   = 0;
constexpr int OFF_B   = 2 * A_BUFSZ;          // 30720
constexpr int SMEM_TOTAL = OFF_B + 2 * B_BUFSZ;  // 61440
constexpr int LROW    = 66;                   // partial row stride (floats)

__device__ __forceinline__ uint32_t smem_u32(const void* p) {
  uint32_t a;
  asm("{ .reg .u64 t; cvta.to.shared.u64 t, %1; cvt.u32.u64 %0, t; }"
      : "=r"(a) : "l"(p));
  return a;
}

// exact 3-way bf16 split of a float pair -> 3 packed bf16x2 {lo=a, hi=b}
__device__ __forceinline__ void split3(float a, float b,
                                       uint32_t& t1, uint32_t& t2,
                                       uint32_t& t3) {
  asm("cvt.rn.bf16x2.f32 %0, %1, %2;" : "=r"(t1) : "f"(b), "f"(a));
  const float a1 = __uint_as_float(t1 << 16);
  const float b1 = __uint_as_float(t1 & 0xffff0000u);
  const float ra = a - a1, rb = b - b1;            // exact residuals
  asm("cvt.rn.bf16x2.f32 %0, %1, %2;" : "=r"(t2) : "f"(rb), "f"(ra));
  const float a2 = __uint_as_float(t2 << 16);
  const float b2 = __uint_as_float(t2 & 0xffff0000u);
  const float ra2 = ra - a2, rb2 = rb - b2;
  asm("cvt.rn.bf16x2.f32 %0, %1, %2;" : "=r"(t3) : "f"(rb2), "f"(ra2));
}

__device__ __forceinline__ void ldsm_x4(uint32_t* r, uint32_t addr) {
  asm volatile(
      "ldmatrix.sync.aligned.m8n8.x4.shared.b16 {%0,%1,%2,%3}, [%4];"
      : "=r"(r[0]), "=r"(r[1]), "=r"(r[2]), "=r"(r[3]) : "r"(addr));
}

__device__ __forceinline__ void mma16816(float* c, const uint32_t* a,
                                         uint32_t b0, uint32_t b1) {
  asm volatile(
      "mma.sync.aligned.m16n8k16.row.col.f32.bf16.bf16.f32 "
      "{%0,%1,%2,%3}, {%4,%5,%6,%7}, {%8,%9}, {%0,%1,%2,%3};"
      : "+f"(c[0]), "+f"(c[1]), "+f"(c[2]), "+f"(c[3])
      : "r"(a[0]), "r"(a[1]), "r"(a[2]), "r"(a[3]), "r"(b0), "r"(b1));
}

}  // namespace

__global__ void __launch_bounds__(NTHREADS, 2)
gate_kernel(const float* __restrict__ x, const float* __restrict__ w,
            float* __restrict__ outw, float* __restrict__ outi)
{
  extern __shared__ __align__(16) char smem[];
  const uint32_t sb = smem_u32(smem);

  const int tid  = threadIdx.x;
  const int wid  = tid >> 5;
  const int lane = tid & 31;
  const int wM   = wid >> 2;        // 0..1 : token rows wM*32..+31
  const int wN   = (wid >> 1) & 1;  // 0..1 : experts wN*32..+31
  const int ks   = wid & 1;         // k16 step within chunk
  const int tile0 = blockIdx.x * TILE_M;

  // per-lane ldmatrix offsets (bytes) within a term tile
  const uint32_t aOff =
      (uint32_t)((wM * 32 + (lane & 15)) * ROWB +
                 (ks * 16 + ((lane >> 4) & 1) * 8) * 2);
  const uint32_t bOff =
      (uint32_t)((wN * 32 + (lane & 7) + ((lane >> 4) & 1) * 8) * ROWB +
                 (ks * 16 + ((lane >> 3) & 1) * 8) * 2);

  // ---- global-load mapping: per chunk, x = 512 float4, w = 512 float4 -----
  const float4* __restrict__ x4 = reinterpret_cast<const float4*>(x);
  const float4* __restrict__ w4 = reinterpret_cast<const float4*>(w);
  const int rowF4 = KDIM / 4;  // 512

  int xtok[2], xk4[2], wexp[2], wk4[2];
  long xg[2], wg[2];
#pragma unroll
  for (int i = 0; i < 2; ++i) {
    const int f = tid + i * NTHREADS;
    xtok[i] = f >> 3;
    xk4[i]  = f & 7;
    xg[i]   = (long)(tile0 + xtok[i]) * rowF4 + xk4[i];
    wexp[i] = f >> 3;
    wk4[i]  = f & 7;
    wg[i]   = (long)wexp[i] * rowF4 + wk4[i];
  }

  // store one float4's 3 bf16-term pairs into a tile set
  auto store_x = [&](int buf, int i, const float4& v) {
    uint32_t p1a, p2a, p3a, p1b, p2b, p3b;
    split3(v.x, v.y, p1a, p2a, p3a);
    split3(v.z, v.w, p1b, p2b, p3b);
    char* base = smem + OFF_A + buf * A_BUFSZ + xtok[i] * ROWB + xk4[i] * 8;
    *reinterpret_cast<uint2*>(base + 0 * A_TERM) = make_uint2(p1a, p1b);
    *reinterpret_cast<uint2*>(base + 1 * A_TERM) = make_uint2(p2a, p2b);
    *reinterpret_cast<uint2*>(base + 2 * A_TERM) = make_uint2(p3a, p3b);
  };
  auto store_w = [&](int buf, int i, const float4& v) {
    uint32_t p1a, p2a, p3a, p1b, p2b, p3b;
    split3(v.x, v.y, p1a, p2a, p3a);
    split3(v.z, v.w, p1b, p2b, p3b);
    char* base = smem + OFF_B + buf * B_BUFSZ + wexp[i] * ROWB + wk4[i] * 8;
    *reinterpret_cast<uint2*>(base + 0 * B_TERM) = make_uint2(p1a, p1b);
    *reinterpret_cast<uint2*>(base + 1 * B_TERM) = make_uint2(p2a, p2b);
    *reinterpret_cast<uint2*>(base + 2 * B_TERM) = make_uint2(p3a, p3b);
  };

  // ---- prologue: chunk 0 -> buf 0 ------------------------------------------
  {
    float4 xv[2], wv[2];
#pragma unroll
    for (int i = 0; i < 2; ++i) { xv[i] = x4[xg[i]]; wv[i] = w4[wg[i]]; }
#pragma unroll
    for (int i = 0; i < 2; ++i) { store_x(0, i, xv[i]); store_w(0, i, wv[i]); }
  }
  __syncthreads();

  // ---- accumulators: 2 m16 x 4 n8 tiles ------------------------------------
  float acc[2][4][4];
#pragma unroll
  for (int mt = 0; mt < 2; ++mt)
#pragma unroll
    for (int nt = 0; nt < 4; ++nt)
#pragma unroll
      for (int r = 0; r < 4; ++r) acc[mt][nt][r] = 0.0f;

  // ---- mainloop -------------------------------------------------------------
  for (int c = 0; c < NCHUNK; ++c) {
    const int buf = c & 1;

    float4 xv[2], wv[2];
    if (c + 1 < NCHUNK) {
      const long off = (long)(c + 1) * (CHUNK / 4);
#pragma unroll
      for (int i = 0; i < 2; ++i) {
        xv[i] = x4[xg[i] + off];
        wv[i] = w4[wg[i] + off];
      }
    }

    const uint32_t baseA = sb + OFF_A + buf * A_BUFSZ;
    const uint32_t baseB = sb + OFF_B + buf * B_BUFSZ;

    // B fragments for all 3 terms (non-trans ldmatrix)
    uint32_t bf[3][2][4];
#pragma unroll
    for (int tb = 0; tb < 3; ++tb)
#pragma unroll
      for (int ng = 0; ng < 2; ++ng)
        ldsm_x4(bf[tb][ng],
                baseB + tb * B_TERM + ng * (16 * ROWB) + bOff);

    // triangular term loop: (ta,tb) in {00,01,02,10,11,20}
#pragma unroll
    for (int ta = 0; ta < 3; ++ta) {
      uint32_t af[2][4];
#pragma unroll
      for (int mt = 0; mt < 2; ++mt)
        ldsm_x4(af[mt], baseA + ta * A_TERM + mt * (16 * ROWB) + aOff);
#pragma unroll
      for (int tb = 0; tb < 3; ++tb) {
        if (ta + tb > 2) continue;
#pragma unroll
        for (int mt = 0; mt < 2; ++mt)
#pragma unroll
          for (int nt = 0; nt < 4; ++nt)
            mma16816(acc[mt][nt], af[mt],
                     bf[tb][nt >> 1][(nt & 1) * 2],
                     bf[tb][nt >> 1][(nt & 1) * 2 + 1]);
      }
    }

    if (c + 1 < NCHUNK) {
      const int nb = buf ^ 1;
#pragma unroll
      for (int i = 0; i < 2; ++i) {
        store_x(nb, i, xv[i]);
        store_w(nb, i, wv[i]);
      }
    }
    __syncthreads();
  }

  // ---- write K-split partial logits (aliases mm tiles; all reads done) -----
  float* partial = reinterpret_cast<float*>(smem);
#pragma unroll
  for (int mt = 0; mt < 2; ++mt)
#pragma unroll
    for (int nt = 0; nt < 4; ++nt) {
      const int tok0 = wM * 32 + mt * 16 + (lane >> 2);
      const int e0   = wN * 32 + nt * 8 + (lane & 3) * 2;
      float* p = partial + (ks * TILE_M + tok0) * LROW + e0;
      *reinterpret_cast<float2*>(p) =
          make_float2(acc[mt][nt][0], acc[mt][nt][1]);
      *reinterpret_cast<float2*>(p + 8 * LROW) =
          make_float2(acc[mt][nt][2], acc[mt][nt][3]);
    }
  __syncthreads();

  // ---- combine + softmax (FTZ like XLA:GPU) + stable top-6 -----------------
  if (tid < TILE_M) {
    const int tok = tid;
    const float* p0 = partial + tok * LROW;
    const float* p1 = partial + (TILE_M + tok) * LROW;

    float l[NEXP];
    float mx = -CUDART_INF_F;
#pragma unroll
    for (int e = 0; e < NEXP; ++e) {
      l[e] = p0[e] + p1[e];
      mx = fmaxf(mx, l[e]);
    }

    float sum = 0.0f;
#pragma unroll
    for (int e = 0; e < NEXP; ++e) {
      l[e] = expf(l[e] - mx);
      sum += l[e];
    }

    float bv[K_TOP];
    int   bi[K_TOP];
#pragma unroll
    for (int j = 0; j < K_TOP; ++j) { bv[j] = -CUDART_INF_F; bi[j] = 0; }

#pragma unroll
    for (int e = 0; e < NEXP; ++e) {
      float s = l[e] / sum;
      // XLA:GPU softmax is FTZ: subnormal scores flush to exactly 0.0 and
      // top_k tie-breaks among zeros by lowest index. Replicate.
      if (s < FP32_MIN_NORMAL) s = 0.0f;
      if (s > bv[K_TOP - 1]) {
        bv[K_TOP - 1] = s;
        bi[K_TOP - 1] = e;
        // strict '>' keeps lowest-index-first among equal scores
#pragma unroll
        for (int j = K_TOP - 1; j > 0; --j) {
          if (bv[j] > bv[j - 1]) {
            const float tv = bv[j]; bv[j] = bv[j - 1]; bv[j - 1] = tv;
            const int   ti = bi[j]; bi[j] = bi[j - 1]; bi[j - 1] = ti;
          }
        }
      }
    }

    const long gt = tile0 + tok;
#pragma unroll
    for (int j = 0; j < K_TOP; ++j) {
      outw[gt * K_TOP + j] = bv[j];
      outi[gt * K_TOP + j] = (float)bi[j];
    }
  }
}

extern "C" void kernel_launch(void* const* d_in, const int* in_sizes, int n_in,
                              void* d_out, int out_size) {
  const float* a = (const float*)d_in[0];
  const float* b = (const float*)d_in[1];
  const float* x = a;
  const float* w = b;
  if (n_in >= 2 && in_sizes[0] == NEXP * KDIM && in_sizes[1] == TOKENS * KDIM) {
    x = b; w = a;
  }

  float* out  = (float*)d_out;
  float* outw = out;                         // weights [16384, 6]
  float* outi = out + (long)TOKENS * K_TOP;  // indices (as float) [16384, 6]

  static bool attr_set = false;
  if (!attr_set) {
    cudaFuncSetAttribute(gate_kernel,
                         cudaFuncAttributeMaxDynamicSharedMemorySize,
                         SMEM_TOTAL);
    attr_set = true;
  }

  gate_kernel<<<TOKENS / TILE_M, NTHREADS, SMEM_TOTAL>>>(x, w, outw, outi);
}

// round 16
// speedup vs baseline: 1.5310x; 1.5310x over previous
#include <cuda_runtime.h>
#include <cuda_fp16.h>
#include <math_constants.h>
#include <cstdint>

namespace {

constexpr int TOKENS   = 16384;
constexpr int NEXP     = 64;
constexpr int KDIM     = 2048;
constexpr int K_TOP    = 6;
constexpr int TILE_M   = 128;        // tokens per CTA
constexpr int CHUNK    = 64;         // k per chunk
constexpr int NCHUNK   = KDIM / CHUNK;  // 32
constexpr int NTHREADS = 256;        // 8 warps: 2(M) x 2(N) x 2(Ksplit)
constexpr float FP32_MIN_NORMAL = 1.17549435e-38f;  // 2^-126

// fp16 tile rows: 64 halves = 128B + 16B pad -> ldmatrix conflict-free
constexpr int ROWB    = 144;
constexpr int A_TERM  = TILE_M * ROWB;        // 18432 B
constexpr int A_BUFSZ = 2 * A_TERM;           // 36864 B (2 terms)
constexpr int B_TERM  = NEXP * ROWB;          // 9216 B
constexpr int B_BUFSZ = 2 * B_TERM;           // 18432 B
constexpr int OFF_A   = 0;
constexpr int OFF_B   = 2 * A_BUFSZ;          // 73728
constexpr int SMEM_TOTAL = OFF_B + 2 * B_BUFSZ;  // 110592
constexpr int LROW    = 66;                   // partial row stride (floats)

__device__ __forceinline__ uint32_t smem_u32(const void* p) {
  uint32_t a;
  asm("{ .reg .u64 t; cvta.to.shared.u64 t, %1; cvt.u32.u64 %0, t; }"
      : "=r"(a) : "l"(p));
  return a;
}

// exact 2-way fp16 split of a float pair -> 2 packed f16x2 {lo=a, hi=b}
// (residuals are exact in fp32; fp16 products are exact in fp32 accum)
__device__ __forceinline__ void split2(float a, float b,
                                       uint32_t& t1, uint32_t& t2) {
  asm("cvt.rn.f16x2.f32 %0, %1, %2;" : "=r"(t1) : "f"(b), "f"(a));
  const __half2 h1 = *reinterpret_cast<const __half2*>(&t1);
  const float ra = a - __half2float(h1.x);
  const float rb = b - __half2float(h1.y);
  asm("cvt.rn.f16x2.f32 %0, %1, %2;" : "=r"(t2) : "f"(rb), "f"(ra));
}

__device__ __forceinline__ void ldsm_x4(uint32_t* r, uint32_t addr) {
  asm volatile(
      "ldmatrix.sync.aligned.m8n8.x4.shared.b16 {%0,%1,%2,%3}, [%4];"
      : "=r"(r[0]), "=r"(r[1]), "=r"(r[2]), "=r"(r[3]) : "r"(addr));
}

__device__ __forceinline__ void mma16816(float* c, const uint32_t* a,
                                         uint32_t b0, uint32_t b1) {
  asm volatile(
      "mma.sync.aligned.m16n8k16.row.col.f32.f16.f16.f32 "
      "{%0,%1,%2,%3}, {%4,%5,%6,%7}, {%8,%9}, {%0,%1,%2,%3};"
      : "+f"(c[0]), "+f"(c[1]), "+f"(c[2]), "+f"(c[3])
      : "r"(a[0]), "r"(a[1]), "r"(a[2]), "r"(a[3]), "r"(b0), "r"(b1));
}

}  // namespace

__global__ void __launch_bounds__(NTHREADS, 1)
gate_kernel(const float* __restrict__ x, const float* __restrict__ w,
            float* __restrict__ outw, float* __restrict__ outi)
{
  extern __shared__ __align__(16) char smem[];
  const uint32_t sb = smem_u32(smem);

  const int tid  = threadIdx.x;
  const int wid  = tid >> 5;
  const int lane = tid & 31;
  const int wM   = wid >> 2;        // 0..1 : token rows wM*64..+63
  const int wN   = (wid >> 1) & 1;  // 0..1 : experts wN*32..+31
  const int ks   = wid & 1;         // handles ksteps {2ks, 2ks+1} of 4
  const int tile0 = blockIdx.x * TILE_M;

  // per-lane ldmatrix lane offsets (bytes), k-step added in-loop
  const uint32_t aLane =
      (uint32_t)((wM * 64 + (lane & 15)) * ROWB + ((lane >> 4) & 1) * 16);
  const uint32_t bLane =
      (uint32_t)((wN * 32 + (lane & 7) + ((lane >> 4) & 1) * 8) * ROWB +
                 ((lane >> 3) & 1) * 16);

  // ---- global-load mapping: per chunk, x = 2048 float4, w = 1024 float4 ---
  const float4* __restrict__ x4 = reinterpret_cast<const float4*>(x);
  const float4* __restrict__ w4 = reinterpret_cast<const float4*>(w);
  const int rowF4 = KDIM / 4;  // 512

  int xtok[8], xk4[8], wexp[4], wk4[4];
  long xg[8], wg[4];
#pragma unroll
  for (int i = 0; i < 8; ++i) {
    const int f = tid + i * NTHREADS;
    xtok[i] = f >> 4;            // 0..127
    xk4[i]  = f & 15;            // float4 index within 64-float chunk row
    xg[i]   = (long)(tile0 + xtok[i]) * rowF4 + xk4[i];
  }
#pragma unroll
  for (int i = 0; i < 4; ++i) {
    const int g = tid + i * NTHREADS;
    wexp[i] = g >> 4;            // 0..63
    wk4[i]  = g & 15;
    wg[i]   = (long)wexp[i] * rowF4 + wk4[i];
  }

  // store one float4's 2 fp16-term pairs into a tile set
  auto store_x = [&](int buf, int i, const float4& v) {
    uint32_t p1a, p2a, p1b, p2b;
    split2(v.x, v.y, p1a, p2a);
    split2(v.z, v.w, p1b, p2b);
    char* base = smem + OFF_A + buf * A_BUFSZ + xtok[i] * ROWB + xk4[i] * 8;
    *reinterpret_cast<uint2*>(base + 0 * A_TERM) = make_uint2(p1a, p1b);
    *reinterpret_cast<uint2*>(base + 1 * A_TERM) = make_uint2(p2a, p2b);
  };
  auto store_w = [&](int buf, int i, const float4& v) {
    uint32_t p1a, p2a, p1b, p2b;
    split2(v.x, v.y, p1a, p2a);
    split2(v.z, v.w, p1b, p2b);
    char* base = smem + OFF_B + buf * B_BUFSZ + wexp[i] * ROWB + wk4[i] * 8;
    *reinterpret_cast<uint2*>(base + 0 * B_TERM) = make_uint2(p1a, p1b);
    *reinterpret_cast<uint2*>(base + 1 * B_TERM) = make_uint2(p2a, p2b);
  };

  // ---- prologue: chunk 0 -> buf 0 ------------------------------------------
  {
    float4 xv[8], wv[4];
#pragma unroll
    for (int i = 0; i < 8; ++i) xv[i] = x4[xg[i]];
#pragma unroll
    for (int i = 0; i < 4; ++i) wv[i] = w4[wg[i]];
#pragma unroll
    for (int i = 0; i < 8; ++i) store_x(0, i, xv[i]);
#pragma unroll
    for (int i = 0; i < 4; ++i) store_w(0, i, wv[i]);
  }
  __syncthreads();

  // ---- accumulators: 4 m16 x 4 n8 tiles ------------------------------------
  float acc[4][4][4];
#pragma unroll
  for (int mt = 0; mt < 4; ++mt)
#pragma unroll
    for (int nt = 0; nt < 4; ++nt)
#pragma unroll
      for (int r = 0; r < 4; ++r) acc[mt][nt][r] = 0.0f;

  // ---- mainloop -------------------------------------------------------------
  for (int c = 0; c < NCHUNK; ++c) {
    const int buf = c & 1;

    float4 xv[8], wv[4];
    if (c + 1 < NCHUNK) {
      const long off = (long)(c + 1) * (CHUNK / 4);
#pragma unroll
      for (int i = 0; i < 8; ++i) xv[i] = x4[xg[i] + off];
#pragma unroll
      for (int i = 0; i < 4; ++i) wv[i] = w4[wg[i] + off];
    }

    const uint32_t baseA = sb + OFF_A + buf * A_BUFSZ;
    const uint32_t baseB = sb + OFF_B + buf * B_BUFSZ;

#pragma unroll
    for (int kk2 = 0; kk2 < 2; ++kk2) {
      const uint32_t kOff = (uint32_t)((ks * 2 + kk2) * 16) * 2;

      // B fragments for both terms (non-trans ldmatrix)
      uint32_t bf[2][2][4];
#pragma unroll
      for (int tb = 0; tb < 2; ++tb)
#pragma unroll
        for (int ng = 0; ng < 2; ++ng)
          ldsm_x4(bf[tb][ng],
                  baseB + tb * B_TERM + ng * (16 * ROWB) + bLane + kOff);

      // term pairs: (ta,tb) in {00, 01, 10}
#pragma unroll
      for (int ta = 0; ta < 2; ++ta) {
        uint32_t af[4][4];
#pragma unroll
        for (int mt = 0; mt < 4; ++mt)
          ldsm_x4(af[mt],
                  baseA + ta * A_TERM + mt * (16 * ROWB) + aLane + kOff);
#pragma unroll
        for (int tb = 0; tb < 2; ++tb) {
          if (ta + tb > 1) continue;
#pragma unroll
          for (int mt = 0; mt < 4; ++mt)
#pragma unroll
            for (int nt = 0; nt < 4; ++nt)
              mma16816(acc[mt][nt], af[mt],
                       bf[tb][nt >> 1][(nt & 1) * 2],
                       bf[tb][nt >> 1][(nt & 1) * 2 + 1]);
        }
      }
    }

    if (c + 1 < NCHUNK) {
      const int nb = buf ^ 1;
#pragma unroll
      for (int i = 0; i < 8; ++i) store_x(nb, i, xv[i]);
#pragma unroll
      for (int i = 0; i < 4; ++i) store_w(nb, i, wv[i]);
    }
    __syncthreads();
  }

  // ---- write K-split partial logits (aliases mm tiles; all reads done) -----
  float* partial = reinterpret_cast<float*>(smem);
#pragma unroll
  for (int mt = 0; mt < 4; ++mt)
#pragma unroll
    for (int nt = 0; nt < 4; ++nt) {
      const int tok0 = wM * 64 + mt * 16 + (lane >> 2);
      const int e0   = wN * 32 + nt * 8 + (lane & 3) * 2;
      float* p = partial + (ks * TILE_M + tok0) * LROW + e0;
      *reinterpret_cast<float2*>(p) =
          make_float2(acc[mt][nt][0], acc[mt][nt][1]);
      *reinterpret_cast<float2*>(p + 8 * LROW) =
          make_float2(acc[mt][nt][2], acc[mt][nt][3]);
    }
  __syncthreads();

  // ---- combine + softmax (FTZ like XLA:GPU) + stable top-6 -----------------
  if (tid < TILE_M) {
    const int tok = tid;
    const float* p0 = partial + tok * LROW;
    const float* p1 = partial + (TILE_M + tok) * LROW;

    float l[NEXP];
    float mx = -CUDART_INF_F;
#pragma unroll
    for (int e = 0; e < NEXP; ++e) {
      l[e] = p0[e] + p1[e];
      mx = fmaxf(mx, l[e]);
    }

    float sum = 0.0f;
#pragma unroll
    for (int e = 0; e < NEXP; ++e) {
      l[e] = expf(l[e] - mx);
      sum += l[e];
    }

    float bv[K_TOP];
    int   bi[K_TOP];
#pragma unroll
    for (int j = 0; j < K_TOP; ++j) { bv[j] = -CUDART_INF_F; bi[j] = 0; }

#pragma unroll
    for (int e = 0; e < NEXP; ++e) {
      float s = l[e] / sum;
      // XLA:GPU softmax is FTZ: subnormal scores flush to exactly 0.0 and
      // top_k tie-breaks among zeros by lowest index. Replicate.
      if (s < FP32_MIN_NORMAL) s = 0.0f;
      if (s > bv[K_TOP - 1]) {
        bv[K_TOP - 1] = s;
        bi[K_TOP - 1] = e;
        // strict '>' keeps lowest-index-first among equal scores
#pragma unroll
        for (int j = K_TOP - 1; j > 0; --j) {
          if (bv[j] > bv[j - 1]) {
            const float tv = bv[j]; bv[j] = bv[j - 1]; bv[j - 1] = tv;
            const int   ti = bi[j]; bi[j] = bi[j - 1]; bi[j - 1] = ti;
          }
        }
      }
    }

    const long gt = tile0 + tok;
#pragma unroll
    for (int j = 0; j < K_TOP; ++j) {
      outw[gt * K_TOP + j] = bv[j];
      outi[gt * K_TOP + j] = (float)bi[j];
    }
  }
}

extern "C" void kernel_launch(void* const* d_in, const int* in_sizes, int n_in,
                              void* d_out, int out_size) {
  const float* a = (const float*)d_in[0];
  const float* b = (const float*)d_in[1];
  const float* x = a;
  const float* w = b;
  if (n_in >= 2 && in_sizes[0] == NEXP * KDIM && in_sizes[1] == TOKENS * KDIM) {
    x = b; w = a;
  }

  float* out  = (float*)d_out;
  float* outw = out;                         // weights [16384, 6]
  float* outi = out + (long)TOKENS * K_TOP;  // indices (as float) [16384, 6]

  static bool attr_set = false;
  if (!attr_set) {
    cudaFuncSetAttribute(gate_kernel,
                         cudaFuncAttributeMaxDynamicSharedMemorySize,
                         SMEM_TOTAL);
    attr_set = true;
  }

  gate_kernel<<<TOKENS / TILE_M, NTHREADS, SMEM_TOTAL>>>(x, w, outw, outi);
}

// round 17
// speedup vs baseline: 1.5408x; 1.0064x over previous
#include <cuda_runtime.h>
#include <cuda_fp16.h>
#include <math_constants.h>
#include <cstdint>

namespace {

constexpr int TOKENS   = 16384;
constexpr int NEXP     = 64;
constexpr int KDIM     = 2048;
constexpr int K_TOP    = 6;
constexpr int TILE_M   = 128;        // tokens per CTA
constexpr int CHUNK    = 64;         // k per chunk
constexpr int NCHUNK   = KDIM / CHUNK;  // 32
constexpr int NTHREADS = 512;        // 16 warps: 4(M) x 2(N) x 2(Ksplit)
constexpr float FP32_MIN_NORMAL = 1.17549435e-38f;  // 2^-126

// fp16 tile rows: 64 halves = 128B + 16B pad -> ldmatrix conflict-free
constexpr int ROWB    = 144;
constexpr int A_TERM  = TILE_M * ROWB;        // 18432 B
constexpr int A_BUFSZ = 2 * A_TERM;           // 36864 B (2 terms)
constexpr int B_TERM  = NEXP * ROWB;          // 9216 B
constexpr int B_BUFSZ = 2 * B_TERM;           // 18432 B
constexpr int OFF_A   = 0;
constexpr int OFF_B   = 2 * A_BUFSZ;          // 73728
constexpr int SMEM_TOTAL = OFF_B + 2 * B_BUFSZ;  // 110592
constexpr int LROW    = 66;                   // partial row stride (floats)

__device__ __forceinline__ uint32_t smem_u32(const void* p) {
  uint32_t a;
  asm("{ .reg .u64 t; cvta.to.shared.u64 t, %1; cvt.u32.u64 %0, t; }"
      : "=r"(a) : "l"(p));
  return a;
}

// exact 2-way fp16 split of a float pair -> 2 packed f16x2 {lo=a, hi=b}
__device__ __forceinline__ void split2(float a, float b,
                                       uint32_t& t1, uint32_t& t2) {
  asm("cvt.rn.f16x2.f32 %0, %1, %2;" : "=r"(t1) : "f"(b), "f"(a));
  const __half2 h1 = *reinterpret_cast<const __half2*>(&t1);
  const float ra = a - __half2float(h1.x);
  const float rb = b - __half2float(h1.y);
  asm("cvt.rn.f16x2.f32 %0, %1, %2;" : "=r"(t2) : "f"(rb), "f"(ra));
}

__device__ __forceinline__ void ldsm_x4(uint32_t* r, uint32_t addr) {
  asm volatile(
      "ldmatrix.sync.aligned.m8n8.x4.shared.b16 {%0,%1,%2,%3}, [%4];"
      : "=r"(r[0]), "=r"(r[1]), "=r"(r[2]), "=r"(r[3]) : "r"(addr));
}

__device__ __forceinline__ void mma16816(float* c, const uint32_t* a,
                                         uint32_t b0, uint32_t b1) {
  asm volatile(
      "mma.sync.aligned.m16n8k16.row.col.f32.f16.f16.f32 "
      "{%0,%1,%2,%3}, {%4,%5,%6,%7}, {%8,%9}, {%0,%1,%2,%3};"
      : "+f"(c[0]), "+f"(c[1]), "+f"(c[2]), "+f"(c[3])
      : "r"(a[0]), "r"(a[1]), "r"(a[2]), "r"(a[3]), "r"(b0), "r"(b1));
}

}  // namespace

__global__ void __launch_bounds__(NTHREADS, 1)
gate_kernel(const float* __restrict__ x, const float* __restrict__ w,
            float* __restrict__ outw, float* __restrict__ outi)
{
  extern __shared__ __align__(16) char smem[];
  const uint32_t sb = smem_u32(smem);

  const int tid  = threadIdx.x;
  const int wid  = tid >> 5;
  const int lane = tid & 31;
  const int wM   = wid >> 2;        // 0..3 : token rows wM*32..+31
  const int wN   = (wid >> 1) & 1;  // 0..1 : experts wN*32..+31
  const int ks   = wid & 1;         // handles ksteps {2ks, 2ks+1} of 4
  const int tile0 = blockIdx.x * TILE_M;

  // per-lane ldmatrix lane offsets (bytes), k-step added in-loop
  const uint32_t aLane =
      (uint32_t)((wM * 32 + (lane & 15)) * ROWB + ((lane >> 4) & 1) * 16);
  const uint32_t bLane =
      (uint32_t)((wN * 32 + (lane & 7) + ((lane >> 4) & 1) * 8) * ROWB +
                 ((lane >> 3) & 1) * 16);

  // ---- global-load mapping: per chunk, x = 2048 float4, w = 1024 float4 ---
  const float4* __restrict__ x4 = reinterpret_cast<const float4*>(x);
  const float4* __restrict__ w4 = reinterpret_cast<const float4*>(w);
  const int rowF4 = KDIM / 4;  // 512

  int xtok[4], xk4[4], wexp[2], wk4[2];
  long xg[4], wg[2];
#pragma unroll
  for (int i = 0; i < 4; ++i) {
    const int f = tid + i * NTHREADS;
    xtok[i] = f >> 4;            // 0..127
    xk4[i]  = f & 15;            // float4 index within 64-float chunk row
    xg[i]   = (long)(tile0 + xtok[i]) * rowF4 + xk4[i];
  }
#pragma unroll
  for (int i = 0; i < 2; ++i) {
    const int g = tid + i * NTHREADS;
    wexp[i] = g >> 4;            // 0..63
    wk4[i]  = g & 15;
    wg[i]   = (long)wexp[i] * rowF4 + wk4[i];
  }

  // store one float4's 2 fp16-term pairs into a tile set
  auto store_x = [&](int buf, int i, const float4& v) {
    uint32_t p1a, p2a, p1b, p2b;
    split2(v.x, v.y, p1a, p2a);
    split2(v.z, v.w, p1b, p2b);
    char* base = smem + OFF_A + buf * A_BUFSZ + xtok[i] * ROWB + xk4[i] * 8;
    *reinterpret_cast<uint2*>(base + 0 * A_TERM) = make_uint2(p1a, p1b);
    *reinterpret_cast<uint2*>(base + 1 * A_TERM) = make_uint2(p2a, p2b);
  };
  auto store_w = [&](int buf, int i, const float4& v) {
    uint32_t p1a, p2a, p1b, p2b;
    split2(v.x, v.y, p1a, p2a);
    split2(v.z, v.w, p1b, p2b);
    char* base = smem + OFF_B + buf * B_BUFSZ + wexp[i] * ROWB + wk4[i] * 8;
    *reinterpret_cast<uint2*>(base + 0 * B_TERM) = make_uint2(p1a, p1b);
    *reinterpret_cast<uint2*>(base + 1 * B_TERM) = make_uint2(p2a, p2b);
  };

  // ---- prologue: chunk 0 -> buf 0 ------------------------------------------
  {
    float4 xv[4], wv[2];
#pragma unroll
    for (int i = 0; i < 4; ++i) xv[i] = x4[xg[i]];
#pragma unroll
    for (int i = 0; i < 2; ++i) wv[i] = w4[wg[i]];
#pragma unroll
    for (int i = 0; i < 4; ++i) store_x(0, i, xv[i]);
#pragma unroll
    for (int i = 0; i < 2; ++i) store_w(0, i, wv[i]);
  }
  __syncthreads();

  // ---- accumulators: 2 m16 x 4 n8 tiles ------------------------------------
  float acc[2][4][4];
#pragma unroll
  for (int mt = 0; mt < 2; ++mt)
#pragma unroll
    for (int nt = 0; nt < 4; ++nt)
#pragma unroll
      for (int r = 0; r < 4; ++r) acc[mt][nt][r] = 0.0f;

  // ---- mainloop -------------------------------------------------------------
  for (int c = 0; c < NCHUNK; ++c) {
    const int buf = c & 1;

    float4 xv[4], wv[2];
    if (c + 1 < NCHUNK) {
      const long off = (long)(c + 1) * (CHUNK / 4);
#pragma unroll
      for (int i = 0; i < 4; ++i) xv[i] = x4[xg[i] + off];
#pragma unroll
      for (int i = 0; i < 2; ++i) wv[i] = w4[wg[i] + off];
    }

    const uint32_t baseA = sb + OFF_A + buf * A_BUFSZ;
    const uint32_t baseB = sb + OFF_B + buf * B_BUFSZ;

#pragma unroll
    for (int kk2 = 0; kk2 < 2; ++kk2) {
      const uint32_t kOff = (uint32_t)((ks * 2 + kk2) * 16) * 2;

      // B fragments for both terms (non-trans ldmatrix)
      uint32_t bf[2][2][4];
#pragma unroll
      for (int tb = 0; tb < 2; ++tb)
#pragma unroll
        for (int ng = 0; ng < 2; ++ng)
          ldsm_x4(bf[tb][ng],
                  baseB + tb * B_TERM + ng * (16 * ROWB) + bLane + kOff);

      // term pairs: (ta,tb) in {00, 01, 10}
#pragma unroll
      for (int ta = 0; ta < 2; ++ta) {
        uint32_t af[2][4];
#pragma unroll
        for (int mt = 0; mt < 2; ++mt)
          ldsm_x4(af[mt],
                  baseA + ta * A_TERM + mt * (16 * ROWB) + aLane + kOff);
#pragma unroll
        for (int tb = 0; tb < 2; ++tb) {
          if (ta + tb > 1) continue;
#pragma unroll
          for (int mt = 0; mt < 2; ++mt)
#pragma unroll
            for (int nt = 0; nt < 4; ++nt)
              mma16816(acc[mt][nt], af[mt],
                       bf[tb][nt >> 1][(nt & 1) * 2],
                       bf[tb][nt >> 1][(nt & 1) * 2 + 1]);
        }
      }
    }

    if (c + 1 < NCHUNK) {
      const int nb = buf ^ 1;
#pragma unroll
      for (int i = 0; i < 4; ++i) store_x(nb, i, xv[i]);
#pragma unroll
      for (int i = 0; i < 2; ++i) store_w(nb, i, wv[i]);
    }
    __syncthreads();
  }

  // ---- write K-split partial logits (aliases mm tiles; all reads done) -----
  float* partial = reinterpret_cast<float*>(smem);
#pragma unroll
  for (int mt = 0; mt < 2; ++mt)
#pragma unroll
    for (int nt = 0; nt < 4; ++nt) {
      const int tok0 = wM * 32 + mt * 16 + (lane >> 2);
      const int e0   = wN * 32 + nt * 8 + (lane & 3) * 2;
      float* p = partial + (ks * TILE_M + tok0) * LROW + e0;
      *reinterpret_cast<float2*>(p) =
          make_float2(acc[mt][nt][0], acc[mt][nt][1]);
      *reinterpret_cast<float2*>(p + 8 * LROW) =
          make_float2(acc[mt][nt][2], acc[mt][nt][3]);
    }
  __syncthreads();

  // ---- combine + softmax (FTZ like XLA:GPU) + stable top-6 -----------------
  if (tid < TILE_M) {
    const int tok = tid;
    const float* p0 = partial + tok * LROW;
    const float* p1 = partial + (TILE_M + tok) * LROW;

    float l[NEXP];
    float mx = -CUDART_INF_F;
#pragma unroll
    for (int e = 0; e < NEXP; ++e) {
      l[e] = p0[e] + p1[e];
      mx = fmaxf(mx, l[e]);
    }

    float sum = 0.0f;
#pragma unroll
    for (int e = 0; e < NEXP; ++e) {
      l[e] = expf(l[e] - mx);
      sum += l[e];
    }

    float bv[K_TOP];
    int   bi[K_TOP];
#pragma unroll
    for (int j = 0; j < K_TOP; ++j) { bv[j] = -CUDART_INF_F; bi[j] = 0; }

#pragma unroll
    for (int e = 0; e < NEXP; ++e) {
      float s = l[e] / sum;
      // XLA:GPU softmax is FTZ: subnormal scores flush to exactly 0.0 and
      // top_k tie-breaks among zeros by lowest index. Replicate.
      if (s < FP32_MIN_NORMAL) s = 0.0f;
      if (s > bv[K_TOP - 1]) {
        bv[K_TOP - 1] = s;
        bi[K_TOP - 1] = e;
        // strict '>' keeps lowest-index-first among equal scores
#pragma unroll
        for (int j = K_TOP - 1; j > 0; --j) {
          if (bv[j] > bv[j - 1]) {
            const float tv = bv[j]; bv[j] = bv[j - 1]; bv[j - 1] = tv;
            const int   ti = bi[j]; bi[j] = bi[j - 1]; bi[j - 1] = ti;
          }
        }
      }
    }

    const long gt = tile0 + tok;
#pragma unroll
    for (int j = 0; j < K_TOP; ++j) {
      outw[gt * K_TOP + j] = bv[j];
      outi[gt * K_TOP + j] = (float)bi[j];
    }
  }
}

extern "C" void kernel_launch(void* const* d_in, const int* in_sizes, int n_in,
                              void* d_out, int out_size) {
  const float* a = (const float*)d_in[0];
  const float* b = (const float*)d_in[1];
  const float* x = a;
  const float* w = b;
  if (n_in >= 2 && in_sizes[0] == NEXP * KDIM && in_sizes[1] == TOKENS * KDIM) {
    x = b; w = a;
  }

  float* out  = (float*)d_out;
  float* outw = out;                         // weights [16384, 6]
  float* outi = out + (long)TOKENS * K_TOP;  // indices (as float) [16384, 6]

  static bool attr_set = false;
  if (!attr_set) {
    cudaFuncSetAttribute(gate_kernel,
                         cudaFuncAttributeMaxDynamicSharedMemorySize,
                         SMEM_TOTAL);
    attr_set = true;
  }

  gate_kernel<<<TOKENS / TILE_M, NTHREADS, SMEM_TOTAL>>>(x, w, outw, outi);
}